// round 5
// baseline (speedup 1.0000x reference)
#include <cuda_runtime.h>
#include <cstdint>
#include <math.h>

// Problem constants
#define BB    32
#define NQ    197
#define NV    1568
#define DIMD  768
#define HH    12
#define FF    8
#define NKC   196
#define NOUT  1569
#define BHN   384
#define KDIM  768

// ---------------- scratch (device globals) ----------------
__device__ float g_q[(size_t)BHN * NQ * 64];
__device__ float g_k[(size_t)BHN * NV * 64];
__device__ float g_v[(size_t)BHN * NV * 64];
__device__ float g_att[(size_t)BHN * NOUT * 64];
__device__ float g_wqT[768 * 768];      // pair-interleaved [N][K]
__device__ float g_wkvT[1536 * 768];
__device__ float g_wpT[768 * 768];

// ======================= helpers =======================
__device__ __forceinline__ uint32_t smem_to_u32(const void* p) {
    uint32_t a;
    asm("{ .reg .u64 t; cvta.to.shared.u64 t, %1; cvt.u32.u64 %0, t; }" : "=r"(a) : "l"(p));
    return a;
}
__device__ __forceinline__ uint32_t to_tf32_rn(float x) {
    uint32_t r;
    asm("cvt.rn.tf32.f32 %0, %1;" : "=r"(r) : "f"(x));
    return r;
}
__device__ __forceinline__ float rnd_tf32(float x) { return __uint_as_float(to_tf32_rn(x)); }
__device__ __forceinline__ float4 f4_rnd(float4 v) {
    v.x = rnd_tf32(v.x); v.y = rnd_tf32(v.y); v.z = rnd_tf32(v.z); v.w = rnd_tf32(v.w);
    return v;
}
// pair-interleave position within 8-k groups: [k0,k4,k1,k5,k2,k6,k3,k7]
__device__ __forceinline__ int p8(int k) { return (k & ~7) | ((k & 3) << 1) | ((k >> 2) & 1); }
// store 8 consecutive k (v0 = k0..k3, v1 = k4..k7) pair-interleaved at dst (word-aligned, 8 words)
__device__ __forceinline__ void sts_pair8(float* dst, float4 v0, float4 v1) {
    *(float4*)dst       = make_float4(v0.x, v1.x, v0.y, v1.y);
    *(float4*)(dst + 4) = make_float4(v0.z, v1.z, v0.w, v1.w);
}
__device__ __forceinline__ void cp_async16(uint32_t smem_addr, const void* gptr) {
    asm volatile("cp.async.cg.shared.global [%0], [%1], 16;"
                 :: "r"(smem_addr), "l"(gptr));
}
#define CP_COMMIT() asm volatile("cp.async.commit_group;" ::: "memory")
#define CP_WAIT(n)  asm volatile("cp.async.wait_group %0;" :: "n"(n) : "memory")

__device__ __forceinline__ void mma_tf32(float* c, const uint32_t* a, const uint32_t* b) {
    asm volatile(
        "mma.sync.aligned.m16n8k8.row.col.f32.tf32.tf32.f32 "
        "{%0,%1,%2,%3}, {%4,%5,%6,%7}, {%8,%9}, {%0,%1,%2,%3};"
        : "+f"(c[0]), "+f"(c[1]), "+f"(c[2]), "+f"(c[3])
        : "r"(a[0]), "r"(a[1]), "r"(a[2]), "r"(a[3]), "r"(b[0]), "r"(b[1]));
}

// FMA-pipe exp
__device__ __forceinline__ float fast_exp(float x) {
    x = fmaxf(x, -87.0f);
    float y = x * 1.4426950408889634f;
    float r = y + 12582912.0f;
    int   n = __float_as_int(r) - 0x4B400000;
    float f = y - (r - 12582912.0f);
    float p = 1.3333558146e-3f;
    p = fmaf(p, f, 9.6181291076e-3f);
    p = fmaf(p, f, 5.5504108664e-2f);
    p = fmaf(p, f, 2.4022650696e-1f);
    p = fmaf(p, f, 6.9314718056e-1f);
    p = fmaf(p, f, 1.0f);
    return __int_as_float(__float_as_int(p) + (n << 23));
}

// ======================= weight transpose + tf32 round + pair-interleave =======================
__global__ __launch_bounds__(256)
void transposeW(const float* __restrict__ src, int which, int K, int N)
{
    float* dst = (which == 0) ? g_wqT : (which == 1) ? g_wkvT : g_wpT;
    __shared__ float t[32][33];
    int bx = blockIdx.x * 32;   // N block
    int by = blockIdx.y * 32;   // K block
    int txl = threadIdx.x & 31;
    int tyl = threadIdx.x >> 5;
#pragma unroll
    for (int j = 0; j < 32; j += 8)
        t[tyl + j][txl] = src[(size_t)(by + tyl + j) * N + bx + txl];
    __syncthreads();
#pragma unroll
    for (int j = 0; j < 32; j += 8)
        dst[(size_t)(bx + tyl + j) * K + by + p8(txl)] = rnd_tf32(t[txl][tyl + j]);
}

// ======================= mma.sync tf32 GEMM (pair-interleaved smem) =======================
constexpr int BM = 128, BN = 128, BK = 32;
constexpr int SK = 40;                         // row stride (words); SK%32==8 -> conflict-free LDS.64
constexpr int AB_WORDS = BM * SK;              // 5120 words per operand
constexpr int STAGE_WORDS = 2 * AB_WORDS;      // 10240
constexpr int GEMM_SMEM = 2 * STAGE_WORDS * 4; // 81920 bytes
constexpr int KT = KDIM / BK;                  // 24

template<int MODE>
__global__ __launch_bounds__(256, 2)
void gemm_tc(const float* __restrict__ A, const float* __restrict__ bias,
             float* __restrict__ Cout, int M)
{
    extern __shared__ float sm[];
    const int tid   = threadIdx.x;
    const int warp  = tid >> 5;
    const int lane  = tid & 31;
    const int group = lane >> 2;
    const int tig   = lane & 3;
    const int wm    = warp & 3;
    const int wn    = warp >> 2;
    const int row0  = blockIdx.y * BM;
    const int col0  = blockIdx.x * BN;

    const float* BT = (MODE == 0) ? g_wqT : (MODE == 1) ? g_wkvT : g_wpT;

    float acc[2][8][4];
#pragma unroll
    for (int mt = 0; mt < 2; mt++)
#pragma unroll
        for (int nt = 0; nt < 8; nt++)
#pragma unroll
            for (int c = 0; c < 4; c++) acc[mt][nt][c] = 0.f;

    // A unit coords: 512 units (row, 8k-group); thread handles rows ar, ar+64 at group ag
    const int ar = tid >> 2;
    const int ag = tid & 3;

    float4 aregs[2][2][2];   // [parity][unit][half]

    auto ldA = [&](int kt, int pbuf) {
#pragma unroll
        for (int u = 0; u < 2; u++) {
            int r = ar + u * 64;
            int grow = row0 + r;
            int k0 = kt * BK + ag * 8;
            if (grow < M) {
                const float* src;
                if (MODE == 2) {
                    int b_ = grow / NOUT;
                    int n_ = grow - b_ * NOUT;
                    int h = k0 >> 6, dd = k0 & 63;
                    src = &g_att[(((size_t)(b_ * HH + h) * NOUT + n_) << 6) + dd];
                } else {
                    src = &A[(size_t)grow * KDIM + k0];
                }
                aregs[pbuf][u][0] = *(const float4*)src;
                aregs[pbuf][u][1] = *(const float4*)(src + 4);
            } else {
                aregs[pbuf][u][0] = make_float4(0.f, 0.f, 0.f, 0.f);
                aregs[pbuf][u][1] = make_float4(0.f, 0.f, 0.f, 0.f);
            }
        }
    };
    auto stA = [&](int s, int pbuf) {
        float* base = sm + s * STAGE_WORDS;
#pragma unroll
        for (int u = 0; u < 2; u++) {
            int r = ar + u * 64;
            sts_pair8(&base[r * SK + ag * 8],
                      f4_rnd(aregs[pbuf][u][0]), f4_rnd(aregs[pbuf][u][1]));
        }
    };
    const uint32_t sb32 = smem_to_u32(sm);
    auto cpB = [&](int kt, int s) {
        uint32_t b32 = sb32 + (uint32_t)(s * STAGE_WORDS + AB_WORDS) * 4;
#pragma unroll
        for (int it = 0; it < 4; it++) {
            int idx = tid + it * 256;
            int n = idx >> 3, c = idx & 7;
            cp_async16(b32 + (uint32_t)(n * SK + c * 4) * 4,
                       &BT[(size_t)(col0 + n) * KDIM + kt * BK + c * 4]);
        }
        CP_COMMIT();
    };

    // prologue
    ldA(0, 0); stA(0, 0); cpB(0, 0);
    ldA(1, 1); cpB(1, 1);

    for (int kt = 0; kt < KT; kt++) {
        const int cur = kt & 1;
        if (kt + 1 < KT) stA(cur ^ 1, (kt + 1) & 1);
        if (kt + 2 < KT) ldA(kt + 2, kt & 1);   // overwrites aregs[cur] (already consumed)
        if (kt + 1 < KT) { CP_WAIT(1); } else { CP_WAIT(0); }
        __syncthreads();

        const float* As = sm + cur * STAGE_WORDS;
        const float* Bs = As + AB_WORDS;
#pragma unroll
        for (int ks = 0; ks < 4; ks++) {
            const int ko = ks * 8 + 2 * tig;
            uint32_t af[2][4];
#pragma unroll
            for (int mt = 0; mt < 2; mt++) {
                int r = wm * 32 + mt * 16 + group;
                float2 lo = *(const float2*)&As[r * SK + ko];
                float2 hi = *(const float2*)&As[(r + 8) * SK + ko];
                af[mt][0] = __float_as_uint(lo.x);
                af[mt][1] = __float_as_uint(hi.x);
                af[mt][2] = __float_as_uint(lo.y);
                af[mt][3] = __float_as_uint(hi.y);
            }
#pragma unroll
            for (int nt = 0; nt < 8; nt++) {
                int n = wn * 64 + nt * 8 + group;
                float2 b = *(const float2*)&Bs[n * SK + ko];
                uint32_t bf[2] = { __float_as_uint(b.x), __float_as_uint(b.y) };
                mma_tf32(acc[0][nt], af[0], bf);
                mma_tf32(acc[1][nt], af[1], bf);
            }
        }
        __syncthreads();
        if (kt + 2 < KT) cpB(kt + 2, cur);
    }

    // ---- epilogue
#pragma unroll
    for (int mt = 0; mt < 2; mt++) {
#pragma unroll
        for (int half = 0; half < 2; half++) {
            int row = row0 + wm * 32 + mt * 16 + group + half * 8;
            if (row >= M) continue;
            int b_, n_;
            if (MODE == 0) { b_ = row / NQ;   n_ = row - b_ * NQ; }
            else if (MODE == 1) { b_ = row / NV; n_ = row - b_ * NV; }
            else { b_ = 0; n_ = 0; }
#pragma unroll
            for (int nt = 0; nt < 8; nt++) {
                int col = col0 + wn * 64 + nt * 8 + tig * 2;
                float v0 = acc[mt][nt][half * 2 + 0];
                float v1 = acc[mt][nt][half * 2 + 1];
                if (MODE == 0) {
                    int h = col >> 6, dd = col & 63;
                    float2 w = make_float2(v0 * 0.125f, v1 * 0.125f);
                    *(float2*)&g_q[(((size_t)(b_ * HH + h) * NQ + n_) << 6) + dd] = w;
                } else if (MODE == 1) {
                    float2 w = make_float2(v0, v1);
                    if (col < DIMD) {
                        int h = col >> 6, dd = col & 63;
                        *(float2*)&g_k[(((size_t)(b_ * HH + h) * NV + n_) << 6) + dd] = w;
                    } else {
                        int c2 = col - DIMD;
                        int h = c2 >> 6, dd = c2 & 63;
                        *(float2*)&g_v[(((size_t)(b_ * HH + h) * NV + n_) << 6) + dd] = w;
                    }
                } else {
                    float2 w = make_float2(v0 + bias[col], v1 + bias[col + 1]);
                    *(float2*)&Cout[(size_t)row * DIMD + col] = w;
                }
            }
        }
    }
}

// ======================= cls-token attention =======================
__global__ __launch_bounds__(256)
void cls_attn()
{
    __shared__ float qsh[64];
    __shared__ float ssh[NV];
    __shared__ float red[40];
    __shared__ float osh[4][64];

    const int bh   = blockIdx.x;
    const int tid  = threadIdx.x;
    const int lane = tid & 31;
    const int warp = tid >> 5;

    if (tid < 64) qsh[tid] = g_q[((size_t)bh * NQ) * 64 + tid];
    __syncthreads();

    for (int j = warp; j < NV; j += 8) {
        const float* kr = &g_k[((size_t)bh * NV + j) * 64];
        float p = qsh[lane] * kr[lane] + qsh[lane + 32] * kr[lane + 32];
#pragma unroll
        for (int o = 16; o > 0; o >>= 1) p += __shfl_xor_sync(0xffffffffu, p, o);
        if (lane == 0) ssh[j] = p;
    }
    __syncthreads();

    float m = -1e30f;
    for (int j = tid; j < NV; j += 256) m = fmaxf(m, ssh[j]);
#pragma unroll
    for (int o = 16; o > 0; o >>= 1) m = fmaxf(m, __shfl_xor_sync(0xffffffffu, m, o));
    if (lane == 0) red[warp] = m;
    __syncthreads();
    if (tid == 0) {
        float mm = red[0];
        for (int w = 1; w < 8; w++) mm = fmaxf(mm, red[w]);
        red[32] = mm;
    }
    __syncthreads();
    m = red[32];

    float s = 0.f;
    for (int j = tid; j < NV; j += 256) {
        float e = fast_exp(ssh[j] - m);
        ssh[j] = e;
        s += e;
    }
#pragma unroll
    for (int o = 16; o > 0; o >>= 1) s += __shfl_xor_sync(0xffffffffu, s, o);
    if (lane == 0) red[8 + warp] = s;
    __syncthreads();
    if (tid == 0) {
        float ss = 0.f;
        for (int w = 0; w < 8; w++) ss += red[8 + w];
        red[33] = 1.f / ss;
    }
    __syncthreads();
    const float inv = red[33];

    const int g = tid >> 6, dd = tid & 63;
    float o = 0.f;
    for (int j = g; j < NV; j += 4)
        o = fmaf(ssh[j], g_v[((size_t)bh * NV + j) * 64 + dd], o);
    osh[g][dd] = o;
    __syncthreads();
    if (tid < 64) {
        float r = (osh[0][tid] + osh[1][tid] + osh[2][tid] + osh[3][tid]) * inv;
        g_att[((size_t)bh * NOUT) * 64 + tid] = r;
    }
}

// ======================= fine attention — tensor cores, interleaved layouts =======================
constexpr int QW = 72;    // Qs [64][72]  pair-interleaved d     (72%32==8 -> conflict-free)
constexpr int KW = 72;    // Ks [224][72] pair-interleaved d
constexpr int VW = 200;   // Vt [64][200] pair-interleaved keys  (200%32==8)
constexpr int SW = 228;   // Ss [64][228] natural
constexpr int Q_OFF = 0;
constexpr int K_OFF = Q_OFF + 64 * QW;    // 4608
constexpr int V_OFF = K_OFF + 224 * KW;   // 20736
constexpr int S_OFF = V_OFF + 64 * VW;    // 33536
constexpr int I_OFF = S_OFF + 64 * SW;    // 48128
constexpr int FINE_SMEM = (I_OFF + 64) * 4;  // 192768 bytes

__global__ __launch_bounds__(256, 1)
void fine_attn()
{
    extern __shared__ float smf[];
    float* Qs = smf + Q_OFF;
    float* Ks = smf + K_OFF;
    float* Vt = smf + V_OFF;
    float* Ss = smf + S_OFF;
    float* Iv = smf + I_OFF;

    const int bh    = blockIdx.x >> 3;
    const int f     = blockIdx.x & 7;
    const int tid   = threadIdx.x;
    const int warp  = tid >> 5;
    const int lane  = tid & 31;
    const int group = lane >> 2;
    const int tig   = lane & 3;

    const float* kg = &g_k[((size_t)bh * NV + (size_t)f * NKC) * 64];
    const float* vg = &g_v[((size_t)bh * NV + (size_t)f * NKC) * 64];

    // ---- K: 224 rows x 8 groups, pair-interleaved + rounded (pad rows zero)
    for (int u = tid; u < 224 * 8; u += 256) {
        int r = u >> 3, g = u & 7;
        float4 v0 = make_float4(0.f, 0.f, 0.f, 0.f), v1 = v0;
        if (r < NKC) {
            v0 = f4_rnd(*(const float4*)&kg[r * 64 + g * 8]);
            v1 = f4_rnd(*(const float4*)&kg[r * 64 + g * 8 + 4]);
        }
        sts_pair8(&Ks[r * KW + g * 8], v0, v1);
    }
    // ---- stage V natural into Ss region [196][68], rounded
    for (int idx = tid; idx < NKC * 16; idx += 256) {
        int j = idx >> 4, d4 = (idx & 15) << 2;
        *(float4*)&Ss[j * 68 + d4] = f4_rnd(*(const float4*)&vg[j * 64 + d4]);
    }
    __syncthreads();
    // ---- transpose -> Vt, pair-interleaved keys, pad keys 196..199 zero
    {
        int d = tid >> 2, jj = tid & 3;
        for (int j = jj; j < NKC; j += 4)
            Vt[d * VW + p8(j)] = Ss[j * 68 + d];
        Vt[d * VW + p8(196 + jj)] = 0.f;
    }
    // (sync below, after Q load, orders transpose reads before S-phase writes)

    for (int qc = 0; qc < 4; qc++) {
        const int rows = (qc == 3) ? (NKC - 192) : 64;

        // ---- Q chunk: 64 rows x 8 groups, pair-interleaved + rounded
        for (int u = tid; u < 512; u += 256) {
            int r = u >> 3, g = u & 7;
            float4 v0 = make_float4(0.f, 0.f, 0.f, 0.f), v1 = v0;
            if (r < rows) {
                const float* qp = &g_q[((size_t)bh * NQ + 1 + qc * 64 + r) * 64 + g * 8];
                v0 = f4_rnd(*(const float4*)qp);
                v1 = f4_rnd(*(const float4*)(qp + 4));
            }
            sts_pair8(&Qs[r * QW + g * 8], v0, v1);
        }
        __syncthreads();

        // ---- S = Q @ K^T : warps 2M x 4N, warp tile 32 x 56
        {
            const int wm = warp & 1, wn = warp >> 1;
            float acc[2][7][4];
#pragma unroll
            for (int mt = 0; mt < 2; mt++)
#pragma unroll
                for (int nt = 0; nt < 7; nt++)
#pragma unroll
                    for (int c = 0; c < 4; c++) acc[mt][nt][c] = 0.f;

#pragma unroll
            for (int ks = 0; ks < 8; ks++) {
                const int ko = ks * 8 + 2 * tig;
                uint32_t af[2][4];
#pragma unroll
                for (int mt = 0; mt < 2; mt++) {
                    int r = wm * 32 + mt * 16 + group;
                    float2 lo = *(const float2*)&Qs[r * QW + ko];
                    float2 hi = *(const float2*)&Qs[(r + 8) * QW + ko];
                    af[mt][0] = __float_as_uint(lo.x);
                    af[mt][1] = __float_as_uint(hi.x);
                    af[mt][2] = __float_as_uint(lo.y);
                    af[mt][3] = __float_as_uint(hi.y);
                }
#pragma unroll
                for (int nt = 0; nt < 7; nt++) {
                    int n = wn * 56 + nt * 8 + group;
                    float2 b = *(const float2*)&Ks[n * KW + ko];
                    uint32_t bf[2] = { __float_as_uint(b.x), __float_as_uint(b.y) };
                    mma_tf32(acc[0][nt], af[0], bf);
                    mma_tf32(acc[1][nt], af[1], bf);
                }
            }
#pragma unroll
            for (int mt = 0; mt < 2; mt++) {
                int r = wm * 32 + mt * 16 + group;
#pragma unroll
                for (int nt = 0; nt < 7; nt++) {
                    int n = wn * 56 + nt * 8 + tig * 2;
                    *(float2*)&Ss[r * SW + n]       = make_float2(acc[mt][nt][0], acc[mt][nt][1]);
                    *(float2*)&Ss[(r + 8) * SW + n] = make_float2(acc[mt][nt][2], acc[mt][nt][3]);
                }
            }
        }
        __syncthreads();

        // ---- softmax: 8 rows per warp, ILP-batched; normalization deferred
        {
            float mx[8], sum[8];
#pragma unroll
            for (int rr = 0; rr < 8; rr++) mx[rr] = -1e30f;
#pragma unroll
            for (int it = 0; it < 7; it++) {
                int j = lane + it * 32;
                if (j < NKC) {
#pragma unroll
                    for (int rr = 0; rr < 8; rr++)
                        mx[rr] = fmaxf(mx[rr], Ss[(warp * 8 + rr) * SW + j]);
                }
            }
#pragma unroll
            for (int o = 16; o > 0; o >>= 1)
#pragma unroll
                for (int rr = 0; rr < 8; rr++)
                    mx[rr] = fmaxf(mx[rr], __shfl_xor_sync(0xffffffffu, mx[rr], o));
#pragma unroll
            for (int rr = 0; rr < 8; rr++) sum[rr] = 0.f;
#pragma unroll
            for (int it = 0; it < 7; it++) {
                int j = lane + it * 32;
                if (j < NKC) {
#pragma unroll
                    for (int rr = 0; rr < 8; rr++) {
                        float* sp = &Ss[(warp * 8 + rr) * SW + j];
                        float e = fast_exp(*sp - mx[rr]);
                        *sp = rnd_tf32(e);
                        sum[rr] += e;
                    }
                }
            }
#pragma unroll
            for (int o = 16; o > 0; o >>= 1)
#pragma unroll
                for (int rr = 0; rr < 8; rr++)
                    sum[rr] += __shfl_xor_sync(0xffffffffu, sum[rr], o);
            if (lane == 0) {
#pragma unroll
                for (int rr = 0; rr < 8; rr++) Iv[warp * 8 + rr] = 1.f / sum[rr];
            }
        }
        __syncthreads();

        // ---- O = P @ V : warps 2M x 4N, warp tile 32 x 16; k over 200 (pads zero)
        {
            const int wm = warp & 1, wn = warp >> 1;
            float acc[2][2][4];
#pragma unroll
            for (int mt = 0; mt < 2; mt++)
#pragma unroll
                for (int nt = 0; nt < 2; nt++)
#pragma unroll
                    for (int c = 0; c < 4; c++) acc[mt][nt][c] = 0.f;

            for (int ks = 0; ks < 25; ks++) {
                const int kc = ks * 8 + tig;       // natural (P in Ss)
                const int ko = ks * 8 + 2 * tig;   // interleaved (Vt)
                uint32_t af[2][4];
#pragma unroll
                for (int mt = 0; mt < 2; mt++) {
                    int r = wm * 32 + mt * 16 + group;
                    af[mt][0] = __float_as_uint(Ss[r * SW + kc]);
                    af[mt][1] = __float_as_uint(Ss[(r + 8) * SW + kc]);
                    af[mt][2] = __float_as_uint(Ss[r * SW + kc + 4]);
                    af[mt][3] = __float_as_uint(Ss[(r + 8) * SW + kc + 4]);
                }
#pragma unroll
                for (int nt = 0; nt < 2; nt++) {
                    int n = wn * 16 + nt * 8 + group;
                    float2 b = *(const float2*)&Vt[n * VW + ko];
                    uint32_t bf[2] = { __float_as_uint(b.x), __float_as_uint(b.y) };
                    mma_tf32(acc[0][nt], af[0], bf);
                    mma_tf32(acc[1][nt], af[1], bf);
                }
            }
#pragma unroll
            for (int mt = 0; mt < 2; mt++) {
#pragma unroll
                for (int half = 0; half < 2; half++) {
                    int rl = wm * 32 + mt * 16 + group + half * 8;
                    int qrow = qc * 64 + rl;
                    if (qrow >= NKC) continue;
                    float iv = Iv[rl];
                    size_t base = ((size_t)bh * NOUT + 1 + (size_t)f * NKC + qrow) * 64;
#pragma unroll
                    for (int nt = 0; nt < 2; nt++) {
                        int col = (warp >> 1) * 16 + nt * 8 + tig * 2;
                        float2 w = make_float2(acc[mt][nt][half * 2] * iv,
                                               acc[mt][nt][half * 2 + 1] * iv);
                        *(float2*)&g_att[base + col] = w;
                    }
                }
            }
        }
        __syncthreads();
    }
}

// ======================= launch =======================
extern "C" void kernel_launch(void* const* d_in, const int* in_sizes, int n_in,
                              void* d_out, int out_size)
{
    const float* x        = (const float*)d_in[0];
    const float* question = (const float*)d_in[1];
    const float* Wq       = (const float*)d_in[2];
    const float* Wkv      = (const float*)d_in[3];
    const float* Wproj    = (const float*)d_in[4];
    const float* bproj    = (const float*)d_in[5];
    float* out = (float*)d_out;

    cudaFuncSetAttribute(fine_attn, cudaFuncAttributeMaxDynamicSharedMemorySize, FINE_SMEM);
    cudaFuncSetAttribute(gemm_tc<0>, cudaFuncAttributeMaxDynamicSharedMemorySize, GEMM_SMEM);
    cudaFuncSetAttribute(gemm_tc<1>, cudaFuncAttributeMaxDynamicSharedMemorySize, GEMM_SMEM);
    cudaFuncSetAttribute(gemm_tc<2>, cudaFuncAttributeMaxDynamicSharedMemorySize, GEMM_SMEM);

    transposeW<<<dim3(768 / 32, 768 / 32), 256>>>(Wq, 0, 768, 768);
    transposeW<<<dim3(1536 / 32, 768 / 32), 256>>>(Wkv, 1, 768, 1536);
    transposeW<<<dim3(768 / 32, 768 / 32), 256>>>(Wproj, 2, 768, 768);

    gemm_tc<0><<<dim3(768 / BN, (BB * NQ + BM - 1) / BM), 256, GEMM_SMEM>>>(
        question, nullptr, nullptr, BB * NQ);

    gemm_tc<1><<<dim3(1536 / BN, (BB * NV) / BM), 256, GEMM_SMEM>>>(
        x, nullptr, nullptr, BB * NV);

    cls_attn<<<BHN, 256>>>();
    fine_attn<<<BHN * FF, 256, FINE_SMEM>>>();

    gemm_tc<2><<<dim3(768 / BN, (BB * NOUT + BM - 1) / BM), 256, GEMM_SMEM>>>(
        nullptr, bproj, out, BB * NOUT);
}

// round 6
// speedup vs baseline: 1.3301x; 1.3301x over previous
#include <cuda_runtime.h>
#include <cstdint>
#include <math.h>

// Problem constants
#define BB    32
#define NQ    197
#define NV    1568
#define DIMD  768
#define HH    12
#define FF    8
#define NKC   196
#define NOUT  1569
#define BHN   384
#define KDIM  768

// ---------------- scratch (device globals) ----------------
__device__ float g_q[(size_t)BHN * NQ * 64];
__device__ float g_k[(size_t)BHN * NV * 64];
__device__ float g_v[(size_t)BHN * NV * 64];
__device__ float g_att[(size_t)BHN * NOUT * 64];
__device__ float g_wqT[768 * 768];      // pair-interleaved [N][K], tf32-rounded
__device__ float g_wkvT[1536 * 768];
__device__ float g_wpT[768 * 768];

// ======================= helpers =======================
__device__ __forceinline__ uint32_t smem_to_u32(const void* p) {
    uint32_t a;
    asm("{ .reg .u64 t; cvta.to.shared.u64 t, %1; cvt.u32.u64 %0, t; }" : "=r"(a) : "l"(p));
    return a;
}
__device__ __forceinline__ uint32_t to_tf32_rn(float x) {
    uint32_t r;
    asm("cvt.rn.tf32.f32 %0, %1;" : "=r"(r) : "f"(x));
    return r;
}
__device__ __forceinline__ float rnd_tf32(float x) { return __uint_as_float(to_tf32_rn(x)); }
__device__ __forceinline__ float4 f4_rnd(float4 v) {
    v.x = rnd_tf32(v.x); v.y = rnd_tf32(v.y); v.z = rnd_tf32(v.z); v.w = rnd_tf32(v.w);
    return v;
}
// pair-interleave position within 8-k groups: [k0,k4,k1,k5,k2,k6,k3,k7]
__device__ __forceinline__ int p8(int k) { return (k & ~7) | ((k & 3) << 1) | ((k >> 2) & 1); }
__device__ __forceinline__ void sts_pair8(float* dst, float4 v0, float4 v1) {
    *(float4*)dst       = make_float4(v0.x, v1.x, v0.y, v1.y);
    *(float4*)(dst + 4) = make_float4(v0.z, v1.z, v0.w, v1.w);
}
__device__ __forceinline__ void cp_async16(uint32_t smem_addr, const void* gptr) {
    asm volatile("cp.async.cg.shared.global [%0], [%1], 16;"
                 :: "r"(smem_addr), "l"(gptr));
}
__device__ __forceinline__ void cp_async16p(uint32_t smem_addr, const void* gptr, bool pred) {
    int sz = pred ? 16 : 0;
    asm volatile("cp.async.cg.shared.global [%0], [%1], 16, %2;"
                 :: "r"(smem_addr), "l"(gptr), "r"(sz));
}
#define CP_COMMIT() asm volatile("cp.async.commit_group;" ::: "memory")
#define CP_WAIT(n)  asm volatile("cp.async.wait_group %0;" :: "n"(n) : "memory")

__device__ __forceinline__ void mma_tf32(float* c, const uint32_t* a, const uint32_t* b) {
    asm volatile(
        "mma.sync.aligned.m16n8k8.row.col.f32.tf32.tf32.f32 "
        "{%0,%1,%2,%3}, {%4,%5,%6,%7}, {%8,%9}, {%0,%1,%2,%3};"
        : "+f"(c[0]), "+f"(c[1]), "+f"(c[2]), "+f"(c[3])
        : "r"(a[0]), "r"(a[1]), "r"(a[2]), "r"(a[3]), "r"(b[0]), "r"(b[1]));
}

// FMA-pipe exp
__device__ __forceinline__ float fast_exp(float x) {
    x = fmaxf(x, -87.0f);
    float y = x * 1.4426950408889634f;
    float r = y + 12582912.0f;
    int   n = __float_as_int(r) - 0x4B400000;
    float f = y - (r - 12582912.0f);
    float p = 1.3333558146e-3f;
    p = fmaf(p, f, 9.6181291076e-3f);
    p = fmaf(p, f, 5.5504108664e-2f);
    p = fmaf(p, f, 2.4022650696e-1f);
    p = fmaf(p, f, 6.9314718056e-1f);
    p = fmaf(p, f, 1.0f);
    return __int_as_float(__float_as_int(p) + (n << 23));
}

// ======================= weight transpose + tf32 round + pair-interleave =======================
__global__ __launch_bounds__(256)
void transposeW(const float* __restrict__ src, int which, int K, int N)
{
    float* dst = (which == 0) ? g_wqT : (which == 1) ? g_wkvT : g_wpT;
    __shared__ float t[32][33];
    int bx = blockIdx.x * 32;   // N block
    int by = blockIdx.y * 32;   // K block
    int txl = threadIdx.x & 31;
    int tyl = threadIdx.x >> 5;
#pragma unroll
    for (int j = 0; j < 32; j += 8)
        t[tyl + j][txl] = src[(size_t)(by + tyl + j) * N + bx + txl];
    __syncthreads();
#pragma unroll
    for (int j = 0; j < 32; j += 8)
        dst[(size_t)(bx + tyl + j) * K + by + p8(txl)] = rnd_tf32(t[txl][tyl + j]);
}

// ======================= mma.sync tf32 GEMM =======================
// A: cp.async natural layout (stride 36), CVT at fragment load (R4 style).
// B: cp.async raw copy of pre-interleaved weights (stride 40), LDS.64 fragments.
constexpr int BM = 128, BN = 128, BK = 32;
constexpr int SKA = 36;                         // A row stride (words)
constexpr int SKB = 40;                         // B row stride (words); 40%32==8 -> LDS.64 conflict-free
constexpr int A_WORDS = BM * SKA;               // 4608
constexpr int B_WORDS = BN * SKB;               // 5120
constexpr int STAGE_WORDS = A_WORDS + B_WORDS;  // 9728
constexpr int GEMM_SMEM = 2 * STAGE_WORDS * 4;  // 77824 bytes
constexpr int KT = KDIM / BK;                   // 24

template<int MODE>
__global__ __launch_bounds__(256, 2)
void gemm_tc(const float* __restrict__ A, const float* __restrict__ bias,
             float* __restrict__ Cout, int M)
{
    extern __shared__ float sm[];
    const uint32_t sb32 = smem_to_u32(sm);
    const int tid   = threadIdx.x;
    const int warp  = tid >> 5;
    const int lane  = tid & 31;
    const int group = lane >> 2;
    const int tig   = lane & 3;
    const int wm    = warp & 3;
    const int wn    = warp >> 2;
    const int row0  = blockIdx.y * BM;
    const int col0  = blockIdx.x * BN;

    const float* BT = (MODE == 0) ? g_wqT : (MODE == 1) ? g_wkvT : g_wpT;

    float acc[2][8][4];
#pragma unroll
    for (int mt = 0; mt < 2; mt++)
#pragma unroll
        for (int nt = 0; nt < 8; nt++)
#pragma unroll
            for (int c = 0; c < 4; c++) acc[mt][nt][c] = 0.f;

    // per-thread cp.async coords: 8 float4 per row-of-32k; 1024 float4 per operand tile
    const int lr  = tid >> 3;          // 0..31
    const int lk4 = (tid & 7) << 2;    // 0,4,...,28

    auto load_stage = [&](int kt, int s) {
        const uint32_t aoff = sb32 + (uint32_t)(s * STAGE_WORDS) * 4;
        const uint32_t boff = sb32 + (uint32_t)(s * STAGE_WORDS + A_WORDS) * 4;
        const int k0 = kt * BK;
#pragma unroll
        for (int it = 0; it < 4; it++) {
            int r = lr + it * 32;
            int grow = row0 + r;
            bool ok = grow < M;
            int gr = ok ? grow : 0;
            const float* src;
            if (MODE == 2) {
                int b_ = gr / NOUT;
                int n_ = gr - b_ * NOUT;
                int kk = k0 + lk4;
                int h = kk >> 6, dd = kk & 63;
                src = &g_att[(((size_t)(b_ * HH + h) * NOUT + n_) << 6) + dd];
            } else {
                src = &A[(size_t)gr * KDIM + k0 + lk4];
            }
            cp_async16p(aoff + (uint32_t)(r * SKA + lk4) * 4, src, ok);
        }
#pragma unroll
        for (int it = 0; it < 4; it++) {
            int r = lr + it * 32;
            cp_async16(boff + (uint32_t)(r * SKB + lk4) * 4,
                       &BT[(size_t)(col0 + r) * KDIM + k0 + lk4]);
        }
        CP_COMMIT();
    };

    load_stage(0, 0);

    for (int kt = 0; kt < KT; kt++) {
        const int cur = kt & 1;
        if (kt + 1 < KT) {
            load_stage(kt + 1, (kt + 1) & 1);
            CP_WAIT(1);
        } else {
            CP_WAIT(0);
        }
        __syncthreads();

        const float* As = sm + cur * STAGE_WORDS;
        const float* Bs = As + A_WORDS;

#pragma unroll
        for (int ks = 0; ks < 4; ks++) {
            const int kc = ks * 8 + tig;        // natural k (A)
            const int ko = ks * 8 + 2 * tig;    // interleaved k (B)
            uint32_t af[2][4];
#pragma unroll
            for (int mt = 0; mt < 2; mt++) {
                int r = wm * 32 + mt * 16 + group;
                af[mt][0] = to_tf32_rn(As[r * SKA + kc]);
                af[mt][1] = to_tf32_rn(As[(r + 8) * SKA + kc]);
                af[mt][2] = to_tf32_rn(As[r * SKA + kc + 4]);
                af[mt][3] = to_tf32_rn(As[(r + 8) * SKA + kc + 4]);
            }
#pragma unroll
            for (int nt = 0; nt < 8; nt++) {
                int n = wn * 64 + nt * 8 + group;
                float2 b = *(const float2*)&Bs[n * SKB + ko];
                uint32_t bf[2] = { __float_as_uint(b.x), __float_as_uint(b.y) };
                mma_tf32(acc[0][nt], af[0], bf);
                mma_tf32(acc[1][nt], af[1], bf);
            }
        }
        __syncthreads();
    }

    // ---- epilogue
#pragma unroll
    for (int mt = 0; mt < 2; mt++) {
#pragma unroll
        for (int half = 0; half < 2; half++) {
            int row = row0 + wm * 32 + mt * 16 + group + half * 8;
            if (row >= M) continue;
            int b_, n_;
            if (MODE == 0) { b_ = row / NQ;   n_ = row - b_ * NQ; }
            else if (MODE == 1) { b_ = row / NV; n_ = row - b_ * NV; }
            else { b_ = 0; n_ = 0; }
#pragma unroll
            for (int nt = 0; nt < 8; nt++) {
                int col = col0 + wn * 64 + nt * 8 + tig * 2;
                float v0 = acc[mt][nt][half * 2 + 0];
                float v1 = acc[mt][nt][half * 2 + 1];
                if (MODE == 0) {
                    int h = col >> 6, dd = col & 63;
                    float2 w = make_float2(v0 * 0.125f, v1 * 0.125f);
                    *(float2*)&g_q[(((size_t)(b_ * HH + h) * NQ + n_) << 6) + dd] = w;
                } else if (MODE == 1) {
                    float2 w = make_float2(v0, v1);
                    if (col < DIMD) {
                        int h = col >> 6, dd = col & 63;
                        *(float2*)&g_k[(((size_t)(b_ * HH + h) * NV + n_) << 6) + dd] = w;
                    } else {
                        int c2 = col - DIMD;
                        int h = c2 >> 6, dd = c2 & 63;
                        *(float2*)&g_v[(((size_t)(b_ * HH + h) * NV + n_) << 6) + dd] = w;
                    }
                } else {
                    float2 w = make_float2(v0 + bias[col], v1 + bias[col + 1]);
                    *(float2*)&Cout[(size_t)row * DIMD + col] = w;
                }
            }
        }
    }
}

// ======================= cls-token attention =======================
__global__ __launch_bounds__(256)
void cls_attn()
{
    __shared__ float qsh[64];
    __shared__ float ssh[NV];
    __shared__ float red[40];
    __shared__ float osh[4][64];

    const int bh   = blockIdx.x;
    const int tid  = threadIdx.x;
    const int lane = tid & 31;
    const int warp = tid >> 5;

    if (tid < 64) qsh[tid] = g_q[((size_t)bh * NQ) * 64 + tid];
    __syncthreads();

    for (int j = warp; j < NV; j += 8) {
        const float* kr = &g_k[((size_t)bh * NV + j) * 64];
        float p = qsh[lane] * kr[lane] + qsh[lane + 32] * kr[lane + 32];
#pragma unroll
        for (int o = 16; o > 0; o >>= 1) p += __shfl_xor_sync(0xffffffffu, p, o);
        if (lane == 0) ssh[j] = p;
    }
    __syncthreads();

    float m = -1e30f;
    for (int j = tid; j < NV; j += 256) m = fmaxf(m, ssh[j]);
#pragma unroll
    for (int o = 16; o > 0; o >>= 1) m = fmaxf(m, __shfl_xor_sync(0xffffffffu, m, o));
    if (lane == 0) red[warp] = m;
    __syncthreads();
    if (tid == 0) {
        float mm = red[0];
        for (int w = 1; w < 8; w++) mm = fmaxf(mm, red[w]);
        red[32] = mm;
    }
    __syncthreads();
    m = red[32];

    float s = 0.f;
    for (int j = tid; j < NV; j += 256) {
        float e = fast_exp(ssh[j] - m);
        ssh[j] = e;
        s += e;
    }
#pragma unroll
    for (int o = 16; o > 0; o >>= 1) s += __shfl_xor_sync(0xffffffffu, s, o);
    if (lane == 0) red[8 + warp] = s;
    __syncthreads();
    if (tid == 0) {
        float ss = 0.f;
        for (int w = 0; w < 8; w++) ss += red[8 + w];
        red[33] = 1.f / ss;
    }
    __syncthreads();
    const float inv = red[33];

    const int g = tid >> 6, dd = tid & 63;
    float o = 0.f;
    for (int j = g; j < NV; j += 4)
        o = fmaf(ssh[j], g_v[((size_t)bh * NV + j) * 64 + dd], o);
    osh[g][dd] = o;
    __syncthreads();
    if (tid < 64) {
        float r = (osh[0][tid] + osh[1][tid] + osh[2][tid] + osh[3][tid]) * inv;
        g_att[((size_t)bh * NOUT) * 64 + tid] = r;
    }
}

// ======================= fine attention (R5 version — kept) =======================
constexpr int QW = 72;    // Qs [64][72]  pair-interleaved d
constexpr int KW = 72;    // Ks [224][72] pair-interleaved d
constexpr int VW = 200;   // Vt [64][200] pair-interleaved keys
constexpr int SW = 228;   // Ss [64][228] natural
constexpr int Q_OFF = 0;
constexpr int K_OFF = Q_OFF + 64 * QW;
constexpr int V_OFF = K_OFF + 224 * KW;
constexpr int S_OFF = V_OFF + 64 * VW;
constexpr int I_OFF = S_OFF + 64 * SW;
constexpr int FINE_SMEM = (I_OFF + 64) * 4;

__global__ __launch_bounds__(256, 1)
void fine_attn()
{
    extern __shared__ float smf[];
    float* Qs = smf + Q_OFF;
    float* Ks = smf + K_OFF;
    float* Vt = smf + V_OFF;
    float* Ss = smf + S_OFF;
    float* Iv = smf + I_OFF;

    const int bh    = blockIdx.x >> 3;
    const int f     = blockIdx.x & 7;
    const int tid   = threadIdx.x;
    const int warp  = tid >> 5;
    const int lane  = tid & 31;
    const int group = lane >> 2;
    const int tig   = lane & 3;

    const float* kg = &g_k[((size_t)bh * NV + (size_t)f * NKC) * 64];
    const float* vg = &g_v[((size_t)bh * NV + (size_t)f * NKC) * 64];

    for (int u = tid; u < 224 * 8; u += 256) {
        int r = u >> 3, g = u & 7;
        float4 v0 = make_float4(0.f, 0.f, 0.f, 0.f), v1 = v0;
        if (r < NKC) {
            v0 = f4_rnd(*(const float4*)&kg[r * 64 + g * 8]);
            v1 = f4_rnd(*(const float4*)&kg[r * 64 + g * 8 + 4]);
        }
        sts_pair8(&Ks[r * KW + g * 8], v0, v1);
    }
    for (int idx = tid; idx < NKC * 16; idx += 256) {
        int j = idx >> 4, d4 = (idx & 15) << 2;
        *(float4*)&Ss[j * 68 + d4] = f4_rnd(*(const float4*)&vg[j * 64 + d4]);
    }
    __syncthreads();
    {
        int d = tid >> 2, jj = tid & 3;
        for (int j = jj; j < NKC; j += 4)
            Vt[d * VW + p8(j)] = Ss[j * 68 + d];
        Vt[d * VW + p8(196 + jj)] = 0.f;
    }

    for (int qc = 0; qc < 4; qc++) {
        const int rows = (qc == 3) ? (NKC - 192) : 64;

        for (int u = tid; u < 512; u += 256) {
            int r = u >> 3, g = u & 7;
            float4 v0 = make_float4(0.f, 0.f, 0.f, 0.f), v1 = v0;
            if (r < rows) {
                const float* qp = &g_q[((size_t)bh * NQ + 1 + qc * 64 + r) * 64 + g * 8];
                v0 = f4_rnd(*(const float4*)qp);
                v1 = f4_rnd(*(const float4*)(qp + 4));
            }
            sts_pair8(&Qs[r * QW + g * 8], v0, v1);
        }
        __syncthreads();

        // ---- S = Q @ K^T
        {
            const int wm = warp & 1, wn = warp >> 1;
            float acc[2][7][4];
#pragma unroll
            for (int mt = 0; mt < 2; mt++)
#pragma unroll
                for (int nt = 0; nt < 7; nt++)
#pragma unroll
                    for (int c = 0; c < 4; c++) acc[mt][nt][c] = 0.f;

#pragma unroll
            for (int ks = 0; ks < 8; ks++) {
                const int ko = ks * 8 + 2 * tig;
                uint32_t af[2][4];
#pragma unroll
                for (int mt = 0; mt < 2; mt++) {
                    int r = wm * 32 + mt * 16 + group;
                    float2 lo = *(const float2*)&Qs[r * QW + ko];
                    float2 hi = *(const float2*)&Qs[(r + 8) * QW + ko];
                    af[mt][0] = __float_as_uint(lo.x);
                    af[mt][1] = __float_as_uint(hi.x);
                    af[mt][2] = __float_as_uint(lo.y);
                    af[mt][3] = __float_as_uint(hi.y);
                }
#pragma unroll
                for (int nt = 0; nt < 7; nt++) {
                    int n = wn * 56 + nt * 8 + group;
                    float2 b = *(const float2*)&Ks[n * KW + ko];
                    uint32_t bf[2] = { __float_as_uint(b.x), __float_as_uint(b.y) };
                    mma_tf32(acc[0][nt], af[0], bf);
                    mma_tf32(acc[1][nt], af[1], bf);
                }
            }
#pragma unroll
            for (int mt = 0; mt < 2; mt++) {
                int r = wm * 32 + mt * 16 + group;
#pragma unroll
                for (int nt = 0; nt < 7; nt++) {
                    int n = wn * 56 + nt * 8 + tig * 2;
                    *(float2*)&Ss[r * SW + n]       = make_float2(acc[mt][nt][0], acc[mt][nt][1]);
                    *(float2*)&Ss[(r + 8) * SW + n] = make_float2(acc[mt][nt][2], acc[mt][nt][3]);
                }
            }
        }
        __syncthreads();

        // ---- softmax: ILP-batched
        {
            float mx[8], sum[8];
#pragma unroll
            for (int rr = 0; rr < 8; rr++) mx[rr] = -1e30f;
#pragma unroll
            for (int it = 0; it < 7; it++) {
                int j = lane + it * 32;
                if (j < NKC) {
#pragma unroll
                    for (int rr = 0; rr < 8; rr++)
                        mx[rr] = fmaxf(mx[rr], Ss[(warp * 8 + rr) * SW + j]);
                }
            }
#pragma unroll
            for (int o = 16; o > 0; o >>= 1)
#pragma unroll
                for (int rr = 0; rr < 8; rr++)
                    mx[rr] = fmaxf(mx[rr], __shfl_xor_sync(0xffffffffu, mx[rr], o));
#pragma unroll
            for (int rr = 0; rr < 8; rr++) sum[rr] = 0.f;
#pragma unroll
            for (int it = 0; it < 7; it++) {
                int j = lane + it * 32;
                if (j < NKC) {
#pragma unroll
                    for (int rr = 0; rr < 8; rr++) {
                        float* sp = &Ss[(warp * 8 + rr) * SW + j];
                        float e = fast_exp(*sp - mx[rr]);
                        *sp = rnd_tf32(e);
                        sum[rr] += e;
                    }
                }
            }
#pragma unroll
            for (int o = 16; o > 0; o >>= 1)
#pragma unroll
                for (int rr = 0; rr < 8; rr++)
                    sum[rr] += __shfl_xor_sync(0xffffffffu, sum[rr], o);
            if (lane == 0) {
#pragma unroll
                for (int rr = 0; rr < 8; rr++) Iv[warp * 8 + rr] = 1.f / sum[rr];
            }
        }
        __syncthreads();

        // ---- O = P @ V
        {
            const int wm = warp & 1, wn = warp >> 1;
            float acc[2][2][4];
#pragma unroll
            for (int mt = 0; mt < 2; mt++)
#pragma unroll
                for (int nt = 0; nt < 2; nt++)
#pragma unroll
                    for (int c = 0; c < 4; c++) acc[mt][nt][c] = 0.f;

            for (int ks = 0; ks < 25; ks++) {
                const int kc = ks * 8 + tig;
                const int ko = ks * 8 + 2 * tig;
                uint32_t af[2][4];
#pragma unroll
                for (int mt = 0; mt < 2; mt++) {
                    int r = wm * 32 + mt * 16 + group;
                    af[mt][0] = __float_as_uint(Ss[r * SW + kc]);
                    af[mt][1] = __float_as_uint(Ss[(r + 8) * SW + kc]);
                    af[mt][2] = __float_as_uint(Ss[r * SW + kc + 4]);
                    af[mt][3] = __float_as_uint(Ss[(r + 8) * SW + kc + 4]);
                }
#pragma unroll
                for (int nt = 0; nt < 2; nt++) {
                    int n = wn * 16 + nt * 8 + group;
                    float2 b = *(const float2*)&Vt[n * VW + ko];
                    uint32_t bf[2] = { __float_as_uint(b.x), __float_as_uint(b.y) };
                    mma_tf32(acc[0][nt], af[0], bf);
                    mma_tf32(acc[1][nt], af[1], bf);
                }
            }
#pragma unroll
            for (int mt = 0; mt < 2; mt++) {
#pragma unroll
                for (int half = 0; half < 2; half++) {
                    int rl = wm * 32 + mt * 16 + group + half * 8;
                    int qrow = qc * 64 + rl;
                    if (qrow >= NKC) continue;
                    float iv = Iv[rl];
                    size_t base = ((size_t)bh * NOUT + 1 + (size_t)f * NKC + qrow) * 64;
#pragma unroll
                    for (int nt = 0; nt < 2; nt++) {
                        int col = (warp >> 1) * 16 + nt * 8 + tig * 2;
                        float2 w = make_float2(acc[mt][nt][half * 2] * iv,
                                               acc[mt][nt][half * 2 + 1] * iv);
                        *(float2*)&g_att[base + col] = w;
                    }
                }
            }
        }
        __syncthreads();
    }
}

// ======================= launch =======================
extern "C" void kernel_launch(void* const* d_in, const int* in_sizes, int n_in,
                              void* d_out, int out_size)
{
    const float* x        = (const float*)d_in[0];
    const float* question = (const float*)d_in[1];
    const float* Wq       = (const float*)d_in[2];
    const float* Wkv      = (const float*)d_in[3];
    const float* Wproj    = (const float*)d_in[4];
    const float* bproj    = (const float*)d_in[5];
    float* out = (float*)d_out;

    cudaFuncSetAttribute(fine_attn, cudaFuncAttributeMaxDynamicSharedMemorySize, FINE_SMEM);
    cudaFuncSetAttribute(gemm_tc<0>, cudaFuncAttributeMaxDynamicSharedMemorySize, GEMM_SMEM);
    cudaFuncSetAttribute(gemm_tc<1>, cudaFuncAttributeMaxDynamicSharedMemorySize, GEMM_SMEM);
    cudaFuncSetAttribute(gemm_tc<2>, cudaFuncAttributeMaxDynamicSharedMemorySize, GEMM_SMEM);

    transposeW<<<dim3(768 / 32, 768 / 32), 256>>>(Wq, 0, 768, 768);
    transposeW<<<dim3(1536 / 32, 768 / 32), 256>>>(Wkv, 1, 768, 1536);
    transposeW<<<dim3(768 / 32, 768 / 32), 256>>>(Wproj, 2, 768, 768);

    gemm_tc<0><<<dim3(768 / BN, (BB * NQ + BM - 1) / BM), 256, GEMM_SMEM>>>(
        question, nullptr, nullptr, BB * NQ);

    gemm_tc<1><<<dim3(1536 / BN, (BB * NV) / BM), 256, GEMM_SMEM>>>(
        x, nullptr, nullptr, BB * NV);

    cls_attn<<<BHN, 256>>>();
    fine_attn<<<BHN * FF, 256, FINE_SMEM>>>();

    gemm_tc<2><<<dim3(768 / BN, (BB * NOUT + BM - 1) / BM), 256, GEMM_SMEM>>>(
        nullptr, bproj, out, BB * NOUT);
}